// round 10
// baseline (speedup 1.0000x reference)
#include <cuda_runtime.h>
#include <cuda_fp16.h>

// Poolpointsinterp R9: spatial binning of points + 2-phase (4 batches each)
// transpose->gather with a 32MB scratch that stays L2-resident.

#define SPATIAL_SCALE 0.25f
#define Nn 8
#define Cc 256
#define Hh 128
#define Ww 128

#define HALF_B   4            // batches per phase
#define NPHASE   2
#define NBINS    2048         // 8 (b) x 16 (y/8) x 16 (x/8), b-major
#define BINS_PER_PHASE 1024

// 4*128*128*256 halves = 32 MB scratch, NHWC within phase:
// [(((b_local)*H + y)*W + x)*C + c]
__device__ __half g_scr[(size_t)HALF_B * Hh * Ww * Cc];
__device__ int g_hist[NBINS];
__device__ int g_off[NBINS + 1];
__device__ int g_cursor[NBINS];
__device__ int g_perm[1 << 18];   // up to 256k points

// ---------------------------------------------------------------------------
// Binning helpers
// ---------------------------------------------------------------------------
__device__ __forceinline__ int bin_of(const float* __restrict__ rois, int p)
{
    int b = (int)rois[p * 3 + 0];
    float x = fmaxf(rois[p * 3 + 1] * SPATIAL_SCALE, 0.0f);
    float y = fmaxf(rois[p * 3 + 2] * SPATIAL_SCALE, 0.0f);
    int y_low = min((int)floorf(y), Hh - 1);
    int x_low = min((int)floorf(x), Ww - 1);
    return (b * 16 + (y_low >> 3)) * 16 + (x_low >> 3);
}

__global__ void zero_kernel()
{
    int i = blockIdx.x * blockDim.x + threadIdx.x;
    if (i < NBINS) g_hist[i] = 0;
}

__global__ void hist_kernel(const float* __restrict__ rois, int P)
{
    int p = blockIdx.x * blockDim.x + threadIdx.x;
    if (p < P) atomicAdd(&g_hist[bin_of(rois, p)], 1);
}

// Single-block Hillis-Steele scan over 2048 counters.
__global__ void __launch_bounds__(1024) scan_kernel()
{
    __shared__ int buf[2][NBINS];
    int tid = threadIdx.x;
    buf[0][tid]        = g_hist[tid];
    buf[0][tid + 1024] = g_hist[tid + 1024];
    __syncthreads();
    int src = 0;
    for (int off = 1; off < NBINS; off <<= 1) {
        int dst = 1 - src;
        int i0 = tid, i1 = tid + 1024;
        buf[dst][i0] = buf[src][i0] + (i0 >= off ? buf[src][i0 - off] : 0);
        buf[dst][i1] = buf[src][i1] + (i1 >= off ? buf[src][i1 - off] : 0);
        __syncthreads();
        src = dst;
    }
    int e0 = (tid == 0) ? 0 : buf[src][tid - 1];
    int e1 = buf[src][tid + 1023];
    g_off[tid] = e0;           g_cursor[tid] = e0;
    g_off[tid + 1024] = e1;    g_cursor[tid + 1024] = e1;
    if (tid == 0) g_off[NBINS] = buf[src][NBINS - 1];
}

__global__ void scatter_kernel(const float* __restrict__ rois, int P)
{
    int p = blockIdx.x * blockDim.x + threadIdx.x;
    if (p < P) {
        int pos = atomicAdd(&g_cursor[bin_of(rois, p)], 1);
        g_perm[pos] = p;
    }
}

// ---------------------------------------------------------------------------
// Transpose for one phase: batches [h*4, h*4+4) -> g_scr (b_local = b - h*4).
// grid = (C/32, HALF_B*H), block = 256.
// ---------------------------------------------------------------------------
__global__ void __launch_bounds__(256) transpose_kernel(const float* __restrict__ feat, int h)
{
    __shared__ float tile[32][129];

    int cb = blockIdx.x * 32;
    int bh = blockIdx.y;               // b_local*H + y
    int b_local = bh / Hh;
    int y  = bh % Hh;
    int b  = h * HALF_B + b_local;
    int tid = threadIdx.x;

    int c  = tid >> 3;
    int xq = tid & 7;
    const float4* src = (const float4*)(feat + (((size_t)b * Cc + cb + c) * Hh + y) * Ww);
    #pragma unroll
    for (int i = 0; i < 4; i++) {
        int f4 = i * 8 + xq;
        float4 v = __ldcs(src + f4);
        tile[c][f4 * 4 + 0] = v.x;
        tile[c][f4 * 4 + 1] = v.y;
        tile[c][f4 * 4 + 2] = v.z;
        tile[c][f4 * 4 + 3] = v.w;
    }
    __syncthreads();

    __half* dstbase = g_scr + (size_t)bh * Ww * Cc + cb;
    #pragma unroll
    for (int it = 0; it < 4; it++) {
        int idx = it * 256 + tid;
        int x = idx >> 3;
        int j = idx & 7;
        __half2 lo = __floats2half2_rn(tile[4 * j + 0][x], tile[4 * j + 1][x]);
        __half2 hi = __floats2half2_rn(tile[4 * j + 2][x], tile[4 * j + 3][x]);
        uint2 pack;
        pack.x = *(const unsigned*)&lo;
        pack.y = *(const unsigned*)&hi;
        *(uint2*)(dstbase + (size_t)x * Cc + 4 * j) = pack;
    }
}

// ---------------------------------------------------------------------------
// ROI math (batch-local base into g_scr).
// ---------------------------------------------------------------------------
struct PointAddr {
    size_t base;
    int dx, dy;
    float w1, w2, w3, w4;
    bool valid;
};

__device__ __forceinline__ PointAddr roi_math(const float* __restrict__ rois, int p, int h)
{
    PointAddr r;
    float rb = rois[p * 3 + 0];
    float rx = rois[p * 3 + 1];
    float ry = rois[p * 3 + 2];
    int bi = (int)rb - h * HALF_B;
    float x = rx * SPATIAL_SCALE;
    float y = ry * SPATIAL_SCALE;

    r.valid = (y >= -1.0f) & (y <= (float)Hh) & (x >= -1.0f) & (x <= (float)Ww);

    y = fmaxf(y, 0.0f);
    x = fmaxf(x, 0.0f);
    int y_low = (int)floorf(y);
    int x_low = (int)floorf(x);
    int dxs = 1, dys = 1;
    if (y_low >= Hh - 1) { y_low = Hh - 1; dys = 0; y = (float)y_low; }
    if (x_low >= Ww - 1) { x_low = Ww - 1; dxs = 0; x = (float)x_low; }

    float ly = y - (float)y_low;
    float lx = x - (float)x_low;
    float hy = 1.0f - ly;
    float hx = 1.0f - lx;
    r.w1 = hy * hx; r.w2 = hy * lx; r.w3 = ly * hx; r.w4 = ly * lx;

    r.base = ((size_t)(bi * Hh + y_low) * Ww + x_low) * 32;
    r.dx = dxs * 32;
    r.dy = dys * (Ww * 32);
    return r;
}

__device__ __forceinline__ void blend_store(
    const uint4& a, const uint4& b4, const uint4& c4, const uint4& d4,
    const PointAddr& r, float* __restrict__ out, int p, int t)
{
    const __half2* ah  = (const __half2*)&a;
    const __half2* bh2 = (const __half2*)&b4;
    const __half2* ch  = (const __half2*)&c4;
    const __half2* dh  = (const __half2*)&d4;

    float o[8];
    #pragma unroll
    for (int i = 0; i < 4; i++) {
        float2 f1 = __half22float2(ah[i]);
        float2 f2 = __half22float2(bh2[i]);
        float2 f3 = __half22float2(ch[i]);
        float2 f4 = __half22float2(dh[i]);
        o[2 * i + 0] = r.w1 * f1.x + r.w2 * f2.x + r.w3 * f3.x + r.w4 * f4.x;
        o[2 * i + 1] = r.w1 * f1.y + r.w2 * f2.y + r.w3 * f3.y + r.w4 * f4.y;
    }
    if (!r.valid) {
        #pragma unroll
        for (int i = 0; i < 8; i++) o[i] = 0.0f;
    }
    float4* dst = (float4*)(out + (size_t)p * Cc + t * 8);
    __stcs(dst + 0, make_float4(o[0], o[1], o[2], o[3]));
    __stcs(dst + 1, make_float4(o[4], o[5], o[6], o[7]));
}

// ---------------------------------------------------------------------------
// Gather for one phase: processes sorted positions in [off[h*1024], off[(h+1)*1024]).
// 2 points/warp, 8 loads batch-issued. block = 256.
// ---------------------------------------------------------------------------
__global__ void __launch_bounds__(256) gather_kernel(
    const float* __restrict__ rois,
    float* __restrict__ out,
    int h)
{
    int start = g_off[h * BINS_PER_PHASE];
    int end   = g_off[(h + 1) * BINS_PER_PHASE];

    int w = blockIdx.x * 8 + (threadIdx.x >> 5);
    int pos0 = start + w * 2;
    if (pos0 >= end) return;
    int t = threadIdx.x & 31;

    int p0 = g_perm[pos0];
    bool has1 = (pos0 + 1 < end);
    int p1 = has1 ? g_perm[pos0 + 1] : p0;

    PointAddr r0 = roi_math(rois, p0, h);
    PointAddr r1 = roi_math(rois, p1, h);

    const uint4* g = (const uint4*)g_scr;
    const uint4* q0 = g + r0.base + t;
    const uint4* q1 = g + r1.base + t;

    uint4 a0 = q0[0];
    uint4 b0 = q0[r0.dx];
    uint4 c0 = q0[r0.dy];
    uint4 d0 = q0[r0.dy + r0.dx];
    uint4 a1 = q1[0];
    uint4 b1 = q1[r1.dx];
    uint4 c1 = q1[r1.dy];
    uint4 d1 = q1[r1.dy + r1.dx];

    blend_store(a0, b0, c0, d0, r0, out, p0, t);
    if (has1)
        blend_store(a1, b1, c1, d1, r1, out, p1, t);
}

extern "C" void kernel_launch(void* const* d_in, const int* in_sizes, int n_in,
                              void* d_out, int out_size)
{
    const float* feat = (const float*)d_in[0];
    const float* rois = (const float*)d_in[1];
    float* out = (float*)d_out;
    int P = in_sizes[1] / 3;

    // Binning: zero -> hist -> scan -> scatter
    zero_kernel<<<(NBINS + 255) / 256, 256>>>();
    hist_kernel<<<(P + 255) / 256, 256>>>(rois, P);
    scan_kernel<<<1, 1024>>>();
    scatter_kernel<<<(P + 255) / 256, 256>>>(rois, P);

    dim3 tgrid(Cc / 32, HALF_B * Hh);
    int gblocks = (P + 15) / 16;   // worst case; warps past range exit early
    for (int h = 0; h < NPHASE; h++) {
        transpose_kernel<<<tgrid, 256>>>(feat, h);
        gather_kernel<<<gblocks, 256>>>(rois, out, h);
    }
}